// round 8
// baseline (speedup 1.0000x reference)
#include <cuda_runtime.h>
#include <cuda_bf16.h>
#include <cstdint>

// ---------------------------------------------------------------------------
// GCNDeep: 4-layer GCN
//   per layer: support = act(h) @ W ; agg = b + segment_sum(w * support[src], dst)
// Strategy:
//   - Build dst-binned CSR once per launch (histogram -> scan -> place).
//     Edge metadata packed as int2 {src, bitcast(weight)} for single-LDG.64 access.
//   - Per layer: SIMT fp32 GEMM (W in smem), then atomic-free warp-per-node
//     gather-aggregate with bias folded in and ReLU applied by the next GEMM.
// ---------------------------------------------------------------------------

#define N_NODES_MAX 50000
#define N_EDGES_MAX 800000
#define FEAT 128

__device__ float g_bufA[N_NODES_MAX * FEAT];   // h / agg
__device__ float g_bufB[N_NODES_MAX * FEAT];   // support
__device__ int   g_counts[N_NODES_MAX];        // per-dst degree
__device__ int   g_rowptr[N_NODES_MAX + 1];    // CSR row pointers
__device__ int   g_pos[N_NODES_MAX];           // placement cursors
__device__ int2  g_edge_p[N_EDGES_MAX];        // {src, bitcast(w)} permuted into dst bins

// ---------------------------------------------------------------------------
// CSR build
// ---------------------------------------------------------------------------
__global__ void hist_kernel(const int* __restrict__ dst, int* __restrict__ counts, int E)
{
    int i = blockIdx.x * blockDim.x + threadIdx.x;
    if (i < E) atomicAdd(&counts[dst[i]], 1);
}

// Single-block exclusive scan over counts[0..n) -> row_ptr (and pos copy).
__global__ void __launch_bounds__(1024) scan_kernel(
    const int* __restrict__ counts, int* __restrict__ row_ptr,
    int* __restrict__ pos, int n)
{
    __shared__ int warp_sums[32];
    __shared__ int carry_s;
    if (threadIdx.x == 0) carry_s = 0;
    __syncthreads();

    const int lane = threadIdx.x & 31;
    const int wid  = threadIdx.x >> 5;

    for (int base = 0; base < n; base += 1024) {
        int i = base + (int)threadIdx.x;
        int v = (i < n) ? counts[i] : 0;
        int s = v;
#pragma unroll
        for (int o = 1; o < 32; o <<= 1) {
            int t = __shfl_up_sync(0xffffffffu, s, o);
            if (lane >= o) s += t;
        }
        if (lane == 31) warp_sums[wid] = s;
        __syncthreads();
        if (wid == 0) {
            int ws = warp_sums[lane];
#pragma unroll
            for (int o = 1; o < 32; o <<= 1) {
                int t = __shfl_up_sync(0xffffffffu, ws, o);
                if (lane >= o) ws += t;
            }
            warp_sums[lane] = ws;
        }
        __syncthreads();
        int incl = s + (wid > 0 ? warp_sums[wid - 1] : 0) + carry_s;
        int excl = incl - v;
        if (i < n) { row_ptr[i] = excl; pos[i] = excl; }
        __syncthreads();
        if (threadIdx.x == 1023) carry_s = incl;
        __syncthreads();
    }
    if (threadIdx.x == 0) row_ptr[n] = carry_s;
}

__global__ void place_kernel(
    const int* __restrict__ src, const int* __restrict__ dst,
    const float* __restrict__ ew, int* __restrict__ pos,
    int2* __restrict__ edge_p, int E)
{
    int i = blockIdx.x * blockDim.x + threadIdx.x;
    if (i >= E) return;
    int p = atomicAdd(&pos[dst[i]], 1);
    edge_p[p] = make_int2(src[i], __float_as_int(ew[i]));
}

// ---------------------------------------------------------------------------
// GEMM: out[M, NOUT] = act(X[M,128]) @ W[128, NOUT]
// BM=64 rows per block, 256 threads. W fully staged in smem, X tile staged
// (optionally ReLU'd on load). Register blocking: RPT rows x 4 cols per thread.
// ---------------------------------------------------------------------------
template <int NOUT, bool RELU>
__global__ void __launch_bounds__(256) gemm_kernel(
    const float* __restrict__ X, const float* __restrict__ W,
    float* __restrict__ out, int M)
{
    constexpr int BM   = 64;
    constexpr int CG   = NOUT / 4;     // threads across N
    constexpr int RG   = 256 / CG;     // row-groups
    constexpr int RPT  = BM / RG;      // rows per thread
    constexpr int XS   = FEAT + 4;     // padded X row stride

    extern __shared__ float smem[];
    float* Ws = smem;                  // [128][NOUT]
    float* Xs = smem + FEAT * NOUT;    // [BM][XS]

    const int tid  = threadIdx.x;
    const int row0 = blockIdx.x * BM;

    for (int i = tid * 4; i < FEAT * NOUT; i += 256 * 4)
        *(float4*)(Ws + i) = *(const float4*)(W + i);

    for (int i = tid * 4; i < BM * FEAT; i += 256 * 4) {
        int r = i >> 7;            // /128
        int k = i & (FEAT - 1);
        int grow = row0 + r;
        float4 v = make_float4(0.f, 0.f, 0.f, 0.f);
        if (grow < M) v = *(const float4*)(X + (size_t)grow * FEAT + k);
        if (RELU) {
            v.x = fmaxf(v.x, 0.f); v.y = fmaxf(v.y, 0.f);
            v.z = fmaxf(v.z, 0.f); v.w = fmaxf(v.w, 0.f);
        }
        *(float4*)(Xs + r * XS + k) = v;
    }
    __syncthreads();

    const int cg    = tid % CG;
    const int rg    = tid / CG;
    const int rbase = rg * RPT;

    float acc[RPT][4];
#pragma unroll
    for (int r = 0; r < RPT; r++)
#pragma unroll
        for (int c = 0; c < 4; c++) acc[r][c] = 0.f;

#pragma unroll
    for (int k0 = 0; k0 < FEAT; k0 += 4) {
        float4 wv[4];
#pragma unroll
        for (int j = 0; j < 4; j++)
            wv[j] = *(float4*)(Ws + (k0 + j) * NOUT + cg * 4);
#pragma unroll
        for (int r = 0; r < RPT; r++) {
            float4 xv = *(float4*)(Xs + (rbase + r) * XS + k0);
#pragma unroll
            for (int c = 0; c < 4; c++) {
                acc[r][c] += xv.x * (&wv[0].x)[c] + xv.y * (&wv[1].x)[c]
                           + xv.z * (&wv[2].x)[c] + xv.w * (&wv[3].x)[c];
            }
        }
    }

#pragma unroll
    for (int r = 0; r < RPT; r++) {
        int grow = row0 + rbase + r;
        if (grow < M) {
            float4 v = make_float4(acc[r][0], acc[r][1], acc[r][2], acc[r][3]);
            *(float4*)(out + (size_t)grow * NOUT + cg * 4) = v;
        }
    }
}

// ---------------------------------------------------------------------------
// Aggregate: one warp per dst node; acc = bias + sum_e w_e * support[src_e].
// Packed edge metadata loaded 32-at-a-time cooperatively (one LDG.64/lane),
// broadcast via shuffle. Two independent accumulators (even/odd edges)
// guarantee >=2 gathers in flight per warp regardless of ptxas scheduling.
// ---------------------------------------------------------------------------
template <int COLS>
__global__ void __launch_bounds__(256) aggregate_kernel(
    const float* __restrict__ support, const int* __restrict__ row_ptr,
    const int2* __restrict__ edge_p,
    const float* __restrict__ bias, float* __restrict__ out, int M)
{
    int warp = (blockIdx.x * blockDim.x + threadIdx.x) >> 5;
    int lane = threadIdx.x & 31;
    if (warp >= M) return;

    const int beg = row_ptr[warp];
    const int end = row_ptr[warp + 1];

    if (COLS == 128) {
        float4 acc0 = ((const float4*)bias)[lane];
        float4 acc1 = make_float4(0.f, 0.f, 0.f, 0.f);
        for (int e = beg; e < end; e += 32) {
            int n = min(32, end - e);
            int s = 0, wbits = 0;
            if (lane < n) {
                int2 m = __ldg(edge_p + e + lane);
                s = m.x; wbits = m.y;
            }
            int j = 0;
#pragma unroll 2
            for (; j + 1 < n; j += 2) {
                int   s0 = __shfl_sync(0xffffffffu, s, j);
                float w0 = __int_as_float(__shfl_sync(0xffffffffu, wbits, j));
                int   s1 = __shfl_sync(0xffffffffu, s, j + 1);
                float w1 = __int_as_float(__shfl_sync(0xffffffffu, wbits, j + 1));
                float4 v0 = ((const float4*)(support + (size_t)s0 * 128))[lane];
                float4 v1 = ((const float4*)(support + (size_t)s1 * 128))[lane];
                acc0.x += w0 * v0.x; acc0.y += w0 * v0.y;
                acc0.z += w0 * v0.z; acc0.w += w0 * v0.w;
                acc1.x += w1 * v1.x; acc1.y += w1 * v1.y;
                acc1.z += w1 * v1.z; acc1.w += w1 * v1.w;
            }
            if (j < n) {
                int   sj = __shfl_sync(0xffffffffu, s, j);
                float wj = __int_as_float(__shfl_sync(0xffffffffu, wbits, j));
                float4 v = ((const float4*)(support + (size_t)sj * 128))[lane];
                acc0.x += wj * v.x; acc0.y += wj * v.y;
                acc0.z += wj * v.z; acc0.w += wj * v.w;
            }
        }
        acc0.x += acc1.x; acc0.y += acc1.y; acc0.z += acc1.z; acc0.w += acc1.w;
        ((float4*)(out + (size_t)warp * 128))[lane] = acc0;
    } else {  // COLS == 64
        float2 acc0 = ((const float2*)bias)[lane];
        float2 acc1 = make_float2(0.f, 0.f);
        for (int e = beg; e < end; e += 32) {
            int n = min(32, end - e);
            int s = 0, wbits = 0;
            if (lane < n) {
                int2 m = __ldg(edge_p + e + lane);
                s = m.x; wbits = m.y;
            }
            int j = 0;
#pragma unroll 2
            for (; j + 1 < n; j += 2) {
                int   s0 = __shfl_sync(0xffffffffu, s, j);
                float w0 = __int_as_float(__shfl_sync(0xffffffffu, wbits, j));
                int   s1 = __shfl_sync(0xffffffffu, s, j + 1);
                float w1 = __int_as_float(__shfl_sync(0xffffffffu, wbits, j + 1));
                float2 v0 = ((const float2*)(support + (size_t)s0 * 64))[lane];
                float2 v1 = ((const float2*)(support + (size_t)s1 * 64))[lane];
                acc0.x += w0 * v0.x; acc0.y += w0 * v0.y;
                acc1.x += w1 * v1.x; acc1.y += w1 * v1.y;
            }
            if (j < n) {
                int   sj = __shfl_sync(0xffffffffu, s, j);
                float wj = __int_as_float(__shfl_sync(0xffffffffu, wbits, j));
                float2 v = ((const float2*)(support + (size_t)sj * 64))[lane];
                acc0.x += wj * v.x; acc0.y += wj * v.y;
            }
        }
        acc0.x += acc1.x; acc0.y += acc1.y;
        ((float2*)(out + (size_t)warp * 64))[lane] = acc0;
    }
}

// ---------------------------------------------------------------------------
// Launch
// ---------------------------------------------------------------------------
static inline int cdiv(int a, int b) { return (a + b - 1) / b; }

extern "C" void kernel_launch(void* const* d_in, const int* in_sizes, int n_in,
                              void* d_out, int out_size)
{
    const float* x    = (const float*)d_in[0];
    const int*   esrc = (const int*)  d_in[1];
    const int*   edst = (const int*)  d_in[2];
    const float* ew   = (const float*)d_in[3];
    const float* W0   = (const float*)d_in[4];
    const float* b0   = (const float*)d_in[5];
    const float* W1   = (const float*)d_in[6];
    const float* b1   = (const float*)d_in[7];
    const float* W2   = (const float*)d_in[8];
    const float* b2   = (const float*)d_in[9];
    const float* W3   = (const float*)d_in[10];
    const float* b3   = (const float*)d_in[11];
    float*       out  = (float*)d_out;

    const int M = in_sizes[0] / FEAT;   // 50000
    const int E = in_sizes[1];          // 800000

    float *bufA, *bufB;
    int *counts, *rowptr, *pos;
    int2 *edge_p;
    cudaGetSymbolAddress((void**)&bufA,   g_bufA);
    cudaGetSymbolAddress((void**)&bufB,   g_bufB);
    cudaGetSymbolAddress((void**)&counts, g_counts);
    cudaGetSymbolAddress((void**)&rowptr, g_rowptr);
    cudaGetSymbolAddress((void**)&pos,    g_pos);
    cudaGetSymbolAddress((void**)&edge_p, g_edge_p);

    const int smem128 = (FEAT * 128 + 64 * (FEAT + 4)) * sizeof(float); // 99328
    const int smem64  = (FEAT * 64  + 64 * (FEAT + 4)) * sizeof(float); // 66560
    cudaFuncSetAttribute(gemm_kernel<128, false>,
                         cudaFuncAttributeMaxDynamicSharedMemorySize, smem128);
    cudaFuncSetAttribute(gemm_kernel<128, true>,
                         cudaFuncAttributeMaxDynamicSharedMemorySize, smem128);
    cudaFuncSetAttribute(gemm_kernel<64, true>,
                         cudaFuncAttributeMaxDynamicSharedMemorySize, smem64);

    const int gemm_blocks = cdiv(M, 64);
    const int agg_blocks  = cdiv(M * 32, 256);   // warp per node, 8 warps/block
    const int e_blocks    = cdiv(E, 256);

    // ---- CSR build (once; reused by all 4 layers) ----
    cudaMemsetAsync(counts, 0, M * sizeof(int));
    hist_kernel<<<e_blocks, 256>>>(edst, counts, E);
    scan_kernel<<<1, 1024>>>(counts, rowptr, pos, M);
    place_kernel<<<e_blocks, 256>>>(esrc, edst, ew, pos, edge_p, E);

    // ---- Layer 0 ----
    gemm_kernel<128, false><<<gemm_blocks, 256, smem128>>>(x, W0, bufB, M);
    aggregate_kernel<128><<<agg_blocks, 256>>>(bufB, rowptr, edge_p, b0, bufA, M);

    // ---- Layer 1 ----
    gemm_kernel<128, true><<<gemm_blocks, 256, smem128>>>(bufA, W1, bufB, M);
    aggregate_kernel<128><<<agg_blocks, 256>>>(bufB, rowptr, edge_p, b1, bufA, M);

    // ---- Layer 2 ----
    gemm_kernel<128, true><<<gemm_blocks, 256, smem128>>>(bufA, W2, bufB, M);
    aggregate_kernel<128><<<agg_blocks, 256>>>(bufB, rowptr, edge_p, b2, bufA, M);

    // ---- Layer 3 (N=64, no relu on output, straight into d_out) ----
    gemm_kernel<64, true><<<gemm_blocks, 256, smem64>>>(bufA, W3, bufB, M);
    aggregate_kernel<64><<<agg_blocks, 256>>>(bufB, rowptr, edge_p, b3, out, M);
}

// round 11
// speedup vs baseline: 1.0827x; 1.0827x over previous
#include <cuda_runtime.h>
#include <cuda_bf16.h>
#include <cstdint>

// ---------------------------------------------------------------------------
// GCNDeep: 4-layer GCN
//   per layer: support = act(h) @ W ; agg = b + segment_sum(w * support[src], dst)
// Strategy:
//   - Build dst-binned CSR once per launch (histogram -> scan -> place).
//     Edge metadata packed as int2 {src, bitcast(weight)} for single-LDG.64 access.
//   - Per layer: SIMT fp32 GEMM (BM=128 x BN=64 tiles, 512 thr, 50% occ),
//     then atomic-free warp-per-node gather-aggregate with bias folded in and
//     ReLU applied by the next GEMM's tile stage.
// ---------------------------------------------------------------------------

#define N_NODES_MAX 50000
#define N_EDGES_MAX 800000
#define FEAT 128

__device__ float g_bufA[N_NODES_MAX * FEAT];   // h / agg
__device__ float g_bufB[N_NODES_MAX * FEAT];   // support
__device__ int   g_counts[N_NODES_MAX];        // per-dst degree
__device__ int   g_rowptr[N_NODES_MAX + 1];    // CSR row pointers
__device__ int   g_pos[N_NODES_MAX];           // placement cursors
__device__ int2  g_edge_p[N_EDGES_MAX];        // {src, bitcast(w)} permuted into dst bins

// ---------------------------------------------------------------------------
// CSR build
// ---------------------------------------------------------------------------
__global__ void hist_kernel(const int* __restrict__ dst, int* __restrict__ counts, int E)
{
    int i = blockIdx.x * blockDim.x + threadIdx.x;
    if (i < E) atomicAdd(&counts[dst[i]], 1);
}

// Single-block exclusive scan over counts[0..n) -> row_ptr (and pos copy).
__global__ void __launch_bounds__(1024) scan_kernel(
    const int* __restrict__ counts, int* __restrict__ row_ptr,
    int* __restrict__ pos, int n)
{
    __shared__ int warp_sums[32];
    __shared__ int carry_s;
    if (threadIdx.x == 0) carry_s = 0;
    __syncthreads();

    const int lane = threadIdx.x & 31;
    const int wid  = threadIdx.x >> 5;

    for (int base = 0; base < n; base += 1024) {
        int i = base + (int)threadIdx.x;
        int v = (i < n) ? counts[i] : 0;
        int s = v;
#pragma unroll
        for (int o = 1; o < 32; o <<= 1) {
            int t = __shfl_up_sync(0xffffffffu, s, o);
            if (lane >= o) s += t;
        }
        if (lane == 31) warp_sums[wid] = s;
        __syncthreads();
        if (wid == 0) {
            int ws = warp_sums[lane];
#pragma unroll
            for (int o = 1; o < 32; o <<= 1) {
                int t = __shfl_up_sync(0xffffffffu, ws, o);
                if (lane >= o) ws += t;
            }
            warp_sums[lane] = ws;
        }
        __syncthreads();
        int incl = s + (wid > 0 ? warp_sums[wid - 1] : 0) + carry_s;
        int excl = incl - v;
        if (i < n) { row_ptr[i] = excl; pos[i] = excl; }
        __syncthreads();
        if (threadIdx.x == 1023) carry_s = incl;
        __syncthreads();
    }
    if (threadIdx.x == 0) row_ptr[n] = carry_s;
}

__global__ void place_kernel(
    const int* __restrict__ src, const int* __restrict__ dst,
    const float* __restrict__ ew, int* __restrict__ pos,
    int2* __restrict__ edge_p, int E)
{
    int i = blockIdx.x * blockDim.x + threadIdx.x;
    if (i >= E) return;
    int p = atomicAdd(&pos[dst[i]], 1);
    edge_p[p] = make_int2(src[i], __float_as_int(ew[i]));
}

// ---------------------------------------------------------------------------
// GEMM: out[M, NOUT] tile = act(X[M,128]) @ W[128, NOUT], split along N.
// Block = BM=128 rows x BN=64 cols, 512 threads, 2 CTAs/SM (98KB smem) ->
// 32 warps/SM (50% occ). Per-thread 4x4 register tile; per 4-k chunk:
// 8 LDS.128 vs 64 FFMA. blockIdx.y selects the 64-wide N-half.
// ---------------------------------------------------------------------------
template <bool RELU>
__global__ void __launch_bounds__(512, 2) gemm_kernel(
    const float* __restrict__ X, const float* __restrict__ W,
    float* __restrict__ out, int M, int NOUT)
{
    constexpr int BM = 128;
    constexpr int BN = 64;
    constexpr int XS = FEAT + 4;       // padded X row stride (floats)

    extern __shared__ float smem[];
    float* Ws = smem;                  // [128][64]
    float* Xs = smem + FEAT * BN;      // [BM][XS]

    const int tid  = threadIdx.x;
    const int row0 = blockIdx.x * BM;
    const int c0   = blockIdx.y * BN;

    // Stage W half: 128 rows x 64 cols (16 float4 per row)
    for (int i = tid; i < FEAT * BN / 4; i += 512) {
        int k = i >> 4;                // row
        int c = (i & 15) * 4;          // col within half
        *(float4*)(Ws + k * BN + c) = *(const float4*)(W + (size_t)k * NOUT + c0 + c);
    }

    // Stage X tile: 128 rows x 128 cols (32 float4 per row), optional ReLU
    for (int i = tid; i < BM * FEAT / 4; i += 512) {
        int r = i >> 5;                // row
        int k = (i & 31) * 4;          // col
        int grow = row0 + r;
        float4 v = make_float4(0.f, 0.f, 0.f, 0.f);
        if (grow < M) v = *(const float4*)(X + (size_t)grow * FEAT + k);
        if (RELU) {
            v.x = fmaxf(v.x, 0.f); v.y = fmaxf(v.y, 0.f);
            v.z = fmaxf(v.z, 0.f); v.w = fmaxf(v.w, 0.f);
        }
        *(float4*)(Xs + r * XS + k) = v;
    }
    __syncthreads();

    const int cg    = tid & 15;        // 16 col-groups x 4 cols
    const int rg    = tid >> 4;        // 32 row-groups
    const int rbase = rg * 4;          // 4 rows per thread

    float acc[4][4];
#pragma unroll
    for (int r = 0; r < 4; r++)
#pragma unroll
        for (int c = 0; c < 4; c++) acc[r][c] = 0.f;

#pragma unroll 4
    for (int k0 = 0; k0 < FEAT; k0 += 4) {
        float4 wv[4];
#pragma unroll
        for (int j = 0; j < 4; j++)
            wv[j] = *(float4*)(Ws + (k0 + j) * BN + cg * 4);
        float4 xv[4];
#pragma unroll
        for (int r = 0; r < 4; r++)
            xv[r] = *(float4*)(Xs + (rbase + r) * XS + k0);
#pragma unroll
        for (int r = 0; r < 4; r++) {
#pragma unroll
            for (int c = 0; c < 4; c++) {
                acc[r][c] += xv[r].x * (&wv[0].x)[c] + xv[r].y * (&wv[1].x)[c]
                           + xv[r].z * (&wv[2].x)[c] + xv[r].w * (&wv[3].x)[c];
            }
        }
    }

#pragma unroll
    for (int r = 0; r < 4; r++) {
        int grow = row0 + rbase + r;
        if (grow < M) {
            float4 v = make_float4(acc[r][0], acc[r][1], acc[r][2], acc[r][3]);
            *(float4*)(out + (size_t)grow * NOUT + c0 + cg * 4) = v;
        }
    }
}

// ---------------------------------------------------------------------------
// Aggregate: one warp per dst node; acc = bias + sum_e w_e * support[src_e].
// Packed edge metadata loaded 32-at-a-time cooperatively (one LDG.64/lane),
// broadcast via shuffle. Two independent accumulators (even/odd edges)
// guarantee >=2 gathers in flight per warp regardless of ptxas scheduling.
// ---------------------------------------------------------------------------
template <int COLS>
__global__ void __launch_bounds__(256) aggregate_kernel(
    const float* __restrict__ support, const int* __restrict__ row_ptr,
    const int2* __restrict__ edge_p,
    const float* __restrict__ bias, float* __restrict__ out, int M)
{
    int warp = (blockIdx.x * blockDim.x + threadIdx.x) >> 5;
    int lane = threadIdx.x & 31;
    if (warp >= M) return;

    const int beg = row_ptr[warp];
    const int end = row_ptr[warp + 1];

    if (COLS == 128) {
        float4 acc0 = ((const float4*)bias)[lane];
        float4 acc1 = make_float4(0.f, 0.f, 0.f, 0.f);
        for (int e = beg; e < end; e += 32) {
            int n = min(32, end - e);
            int s = 0, wbits = 0;
            if (lane < n) {
                int2 m = __ldg(edge_p + e + lane);
                s = m.x; wbits = m.y;
            }
            int j = 0;
#pragma unroll 2
            for (; j + 1 < n; j += 2) {
                int   s0 = __shfl_sync(0xffffffffu, s, j);
                float w0 = __int_as_float(__shfl_sync(0xffffffffu, wbits, j));
                int   s1 = __shfl_sync(0xffffffffu, s, j + 1);
                float w1 = __int_as_float(__shfl_sync(0xffffffffu, wbits, j + 1));
                float4 v0 = ((const float4*)(support + (size_t)s0 * 128))[lane];
                float4 v1 = ((const float4*)(support + (size_t)s1 * 128))[lane];
                acc0.x += w0 * v0.x; acc0.y += w0 * v0.y;
                acc0.z += w0 * v0.z; acc0.w += w0 * v0.w;
                acc1.x += w1 * v1.x; acc1.y += w1 * v1.y;
                acc1.z += w1 * v1.z; acc1.w += w1 * v1.w;
            }
            if (j < n) {
                int   sj = __shfl_sync(0xffffffffu, s, j);
                float wj = __int_as_float(__shfl_sync(0xffffffffu, wbits, j));
                float4 v = ((const float4*)(support + (size_t)sj * 128))[lane];
                acc0.x += wj * v.x; acc0.y += wj * v.y;
                acc0.z += wj * v.z; acc0.w += wj * v.w;
            }
        }
        acc0.x += acc1.x; acc0.y += acc1.y; acc0.z += acc1.z; acc0.w += acc1.w;
        ((float4*)(out + (size_t)warp * 128))[lane] = acc0;
    } else {  // COLS == 64
        float2 acc0 = ((const float2*)bias)[lane];
        float2 acc1 = make_float2(0.f, 0.f);
        for (int e = beg; e < end; e += 32) {
            int n = min(32, end - e);
            int s = 0, wbits = 0;
            if (lane < n) {
                int2 m = __ldg(edge_p + e + lane);
                s = m.x; wbits = m.y;
            }
            int j = 0;
#pragma unroll 2
            for (; j + 1 < n; j += 2) {
                int   s0 = __shfl_sync(0xffffffffu, s, j);
                float w0 = __int_as_float(__shfl_sync(0xffffffffu, wbits, j));
                int   s1 = __shfl_sync(0xffffffffu, s, j + 1);
                float w1 = __int_as_float(__shfl_sync(0xffffffffu, wbits, j + 1));
                float2 v0 = ((const float2*)(support + (size_t)s0 * 64))[lane];
                float2 v1 = ((const float2*)(support + (size_t)s1 * 64))[lane];
                acc0.x += w0 * v0.x; acc0.y += w0 * v0.y;
                acc1.x += w1 * v1.x; acc1.y += w1 * v1.y;
            }
            if (j < n) {
                int   sj = __shfl_sync(0xffffffffu, s, j);
                float wj = __int_as_float(__shfl_sync(0xffffffffu, wbits, j));
                float2 v = ((const float2*)(support + (size_t)sj * 64))[lane];
                acc0.x += wj * v.x; acc0.y += wj * v.y;
            }
        }
        acc0.x += acc1.x; acc0.y += acc1.y;
        ((float2*)(out + (size_t)warp * 64))[lane] = acc0;
    }
}

// ---------------------------------------------------------------------------
// Launch
// ---------------------------------------------------------------------------
static inline int cdiv(int a, int b) { return (a + b - 1) / b; }

extern "C" void kernel_launch(void* const* d_in, const int* in_sizes, int n_in,
                              void* d_out, int out_size)
{
    const float* x    = (const float*)d_in[0];
    const int*   esrc = (const int*)  d_in[1];
    const int*   edst = (const int*)  d_in[2];
    const float* ew   = (const float*)d_in[3];
    const float* W0   = (const float*)d_in[4];
    const float* b0   = (const float*)d_in[5];
    const float* W1   = (const float*)d_in[6];
    const float* b1   = (const float*)d_in[7];
    const float* W2   = (const float*)d_in[8];
    const float* b2   = (const float*)d_in[9];
    const float* W3   = (const float*)d_in[10];
    const float* b3   = (const float*)d_in[11];
    float*       out  = (float*)d_out;

    const int M = in_sizes[0] / FEAT;   // 50000
    const int E = in_sizes[1];          // 800000

    float *bufA, *bufB;
    int *counts, *rowptr, *pos;
    int2 *edge_p;
    cudaGetSymbolAddress((void**)&bufA,   g_bufA);
    cudaGetSymbolAddress((void**)&bufB,   g_bufB);
    cudaGetSymbolAddress((void**)&counts, g_counts);
    cudaGetSymbolAddress((void**)&rowptr, g_rowptr);
    cudaGetSymbolAddress((void**)&pos,    g_pos);
    cudaGetSymbolAddress((void**)&edge_p, g_edge_p);

    // GEMM smem: Ws 128x64 + Xs 128x132 floats = 100352 bytes
    const int gemm_smem = (FEAT * 64 + 128 * (FEAT + 4)) * sizeof(float);
    cudaFuncSetAttribute(gemm_kernel<false>,
                         cudaFuncAttributeMaxDynamicSharedMemorySize, gemm_smem);
    cudaFuncSetAttribute(gemm_kernel<true>,
                         cudaFuncAttributeMaxDynamicSharedMemorySize, gemm_smem);

    const dim3 gemm128_grid(cdiv(M, 128), 2);   // two 64-wide N-halves
    const dim3 gemm64_grid (cdiv(M, 128), 1);   // single 64-wide N
    const int  agg_blocks = cdiv(M * 32, 256);  // warp per node, 8 warps/block
    const int  e_blocks   = cdiv(E, 256);

    // ---- CSR build (once; reused by all 4 layers) ----
    cudaMemsetAsync(counts, 0, M * sizeof(int));
    hist_kernel<<<e_blocks, 256>>>(edst, counts, E);
    scan_kernel<<<1, 1024>>>(counts, rowptr, pos, M);
    place_kernel<<<e_blocks, 256>>>(esrc, edst, ew, pos, edge_p, E);

    // ---- Layer 0 ----
    gemm_kernel<false><<<gemm128_grid, 512, gemm_smem>>>(x, W0, bufB, M, 128);
    aggregate_kernel<128><<<agg_blocks, 256>>>(bufB, rowptr, edge_p, b0, bufA, M);

    // ---- Layer 1 ----
    gemm_kernel<true><<<gemm128_grid, 512, gemm_smem>>>(bufA, W1, bufB, M, 128);
    aggregate_kernel<128><<<agg_blocks, 256>>>(bufB, rowptr, edge_p, b1, bufA, M);

    // ---- Layer 2 ----
    gemm_kernel<true><<<gemm128_grid, 512, gemm_smem>>>(bufA, W2, bufB, M, 128);
    aggregate_kernel<128><<<agg_blocks, 256>>>(bufB, rowptr, edge_p, b2, bufA, M);

    // ---- Layer 3 (NOUT=64, no relu on output, straight into d_out) ----
    gemm_kernel<true><<<gemm64_grid, 512, gemm_smem>>>(bufA, W3, bufB, M, 64);
    aggregate_kernel<64><<<agg_blocks, 256>>>(bufB, rowptr, edge_p, b3, out, M);
}